// round 17
// baseline (speedup 1.0000x reference)
#include <cuda_runtime.h>
#include <math.h>
#include <stdint.h>

// ---------------------------------------------------------------------------
// GDER: out[b] = mean( Rx^2 + Ry^2 ) over valid 498x498 map.
// sum(Gy) is cancellation noise => Gy/sum(Gy) taps ~1e15 and Ry^2 dominates by
// >1e16 relative. Only the Gy path is computed, as a separable conv
// Gy = A(y)*B(x), 1/sum(Gy) folded into vertical taps. sum(Gy) replicated on
// host in numpy's exact f64 pairwise order (validated R1-R16, rel_err ~9e-8).
//
// R17 = R11 (best, 34.1us) + parity-decomposed HORIZ:
// products with tap parity j == window parity use ALIGNED register pairs
// d[i]=(f[2i],f[2i+1]) directly -> 37 fma2 + 2 pack2 instead of 30 fma2 +
// 8 pack2 (~16 MOVs). Plus: LDG.64 for the 5th load (only d[8] needed),
// zeroed-weight edge handling (no per-row predicates; one LOP), pointer
// bump once per 15-row phase.
// ---------------------------------------------------------------------------

#define NB        64
#define W         512
#define OUTW      498
#define TILE      56
#define TILES_Y   9        // 9*56 = 504 >= 498

typedef unsigned long long u64;

struct Weights {
    float hw[8];   // horizontal symmetric taps: hw[0..6] pair weights, hw[7] center
    float vw[7];   // vertical antisymmetric taps (scaled by 1/sum(Gy))
};

__device__ double g_partials[NB * TILES_Y];
__device__ int    g_count[NB];   // zero-initialized; self-resetting

// ---- f32x2 packed helpers (sm_100+) ----
__device__ __forceinline__ u64 pack2(float lo, float hi) {
    u64 r; asm("mov.b64 %0, {%1, %2};" : "=l"(r) : "f"(lo), "f"(hi)); return r;
}
__device__ __forceinline__ void unpack2(u64 v, float& lo, float& hi) {
    asm("mov.b64 {%0, %1}, %2;" : "=f"(lo), "=f"(hi) : "l"(v));
}
__device__ __forceinline__ float lo2(u64 v) { float a, b; unpack2(v, a, b); return a; }
__device__ __forceinline__ float hi2(u64 v) { float a, b; unpack2(v, a, b); return b; }
__device__ __forceinline__ u64 fma2(u64 a, u64 b, u64 c) {
    u64 d; asm("fma.rn.f32x2 %0, %1, %2, %3;" : "=l"(d) : "l"(a), "l"(b), "l"(c)); return d;
}
__device__ __forceinline__ u64 add2(u64 a, u64 b) {
    u64 d; asm("add.rn.f32x2 %0, %1, %2;" : "=l"(d) : "l"(a), "l"(b)); return d;
}
__device__ __forceinline__ u64 neg2(u64 a) { return a ^ 0x8000000080000000ull; }

__global__ __launch_bounds__(128, 4) void gder_kernel(const float* __restrict__ x,
                                                      Weights wt,
                                                      float* __restrict__ out)
{
    const int t     = threadIdx.x;
    const int tileY = blockIdx.x;
    const int batch = blockIdx.y;
    const int y0    = tileY * TILE;
    const float* __restrict__ img = x + (size_t)batch * W * W;

    __shared__ double red[128];

    // packed weights: even taps we[]={hw0,hw2,hw4,hw6}, odd wo[]={hw1,hw3,hw5,hw7}
    u64 we[4], wo[4], vp[7];
    #pragma unroll
    for (int m = 0; m < 4; ++m) {
        we[m] = pack2(wt.hw[2 * m],     wt.hw[2 * m]);
        wo[m] = pack2(wt.hw[2 * m + 1], wt.hw[2 * m + 1]);
    }
    // E-chain weight for m (tap j=2m, mirrored): index m<=3 ? m : 7-m
    #define WE(m) (we[(m) <= 3 ? (m) : 7 - (m)])
    // O-chain weight for m (tap j=2m+1, mirrored): index m<=3 ? m : 6-m
    #define WO(m) (wo[(m) <= 3 ? (m) : 6 - (m)])

    const int c = 4 * t;   // this thread's 4 output columns c..c+3

    // Edge handling at init only:
    //  t <= 123: cb = c, 4x LDG.128 + 1x LDG.64 (d[8]).
    //  t == 124: cb = 496 (loads cols 496..511 in-bounds); d[8] (cols 512,513)
    //            never loaded, zeroed once — feeds only masked outputs >= 498.
    //  t >= 125: cb = 492 (in-bounds); vertical weights zeroed -> outputs = 0.
    const int  cb  = (c <= 496) ? c : 492;
    const bool do9 = (c != 496);

    #pragma unroll
    for (int k = 0; k < 7; ++k) {
        vp[k] = (c >= 500) ? 0ull : pack2(wt.vw[k], wt.vw[k]);
    }
    // oB=(col c+2, c+3) valid iff c+3 <= 497 (t <= 123); zero otherwise
    const u64 mB = (c <= 494) ? ~0ull : 0ull;

    // window: f[0..17]; even pairs d[0..7] are LDG.128 register pairs,
    // d[8]=(f16,f17) is one aligned LDG.64
    union InBuf { float f[18]; u64 d[9]; float4 v[4]; };
    InBuf in;
    in.f[16] = 0.f; in.f[17] = 0.f;

    const float* pp = img + (size_t)y0 * W + cb;

    #define LOAD_ROW_AT(OFFW) do {                                                  \
        in.v[0] = *reinterpret_cast<const float4*>(pp + (OFFW));                    \
        in.v[1] = *reinterpret_cast<const float4*>(pp + (OFFW) + 4);                \
        in.v[2] = *reinterpret_cast<const float4*>(pp + (OFFW) + 8);                \
        in.v[3] = *reinterpret_cast<const float4*>(pp + (OFFW) + 12);               \
        if (do9) in.d[8] = *reinterpret_cast<const u64*>(pp + (OFFW) + 16);         \
    } while (0)

    // parity-decomposed horizontal: all fma2 operands are ALIGNED pairs.
    //   E1 = sum_m hw[2m]  *d[m]    -> (o0 even part, o1 even part)
    //   E2 = sum_m hw[2m]  *d[m+1]  -> (o2 even part, o3 even part)
    //   OA = sum_m hw[2m+1]*d[m]    -> (.,            o0 odd part)
    //   OB = sum_m hw[2m+1]*d[m+1]  -> (o1 odd part,  o2 odd part)
    //   OC = sum_m hw[2m+1]*d[m+2]  -> (o3 odd part,  .)
    #define HORIZ_PAR(hA, hB) do {                                   \
        u64 E1 = 0ull, E2 = 0ull, OA = 0ull, OB = 0ull, OC = 0ull;   \
        _Pragma("unroll")                                            \
        for (int m = 0; m < 8; ++m) {                                \
            E1 = fma2(WE(m), in.d[m], E1);                           \
            E2 = fma2(WE(m), in.d[m + 1], E2);                       \
        }                                                            \
        _Pragma("unroll")                                            \
        for (int m = 0; m < 7; ++m) {                                \
            OA = fma2(WO(m), in.d[m], OA);                           \
            OB = fma2(WO(m), in.d[m + 1], OB);                       \
            OC = fma2(WO(m), in.d[m + 2], OC);                       \
        }                                                            \
        hA = add2(E1, pack2(hi2(OA), lo2(OB)));                      \
        hB = add2(E2, pack2(hi2(OB), lo2(OC)));                      \
    } while (0)

    // vertical for the output whose oldest ring row sits in slot q
    #define VERT(q) do {                                                        \
        u64 aA = 0ull, bA = 0ull, aB = 0ull, bB = 0ull;                         \
        _Pragma("unroll")                                                       \
        for (int k = 0; k < 7; ++k) {                                           \
            aA = fma2(vp[k], rA[((q) + k) % 15], aA);                           \
            bA = fma2(vp[k], rA[((q) + 14 - k) % 15], bA);                      \
            aB = fma2(vp[k], rB[((q) + k) % 15], aB);                           \
            bB = fma2(vp[k], rB[((q) + 14 - k) % 15], bB);                      \
        }                                                                       \
        const u64 oA = add2(aA, neg2(bA));                                      \
        u64 oB = add2(aB, neg2(bB));                                            \
        oB &= mB;                       /* unconditional: mB=~0 for t<=123 */   \
        facc = fma2(oA, oA, facc);                                              \
        facc = fma2(oB, oB, facc);                                              \
    } while (0)

    // ring of horizontal results: slot j holds row y0+j (mod 15)
    u64 rA[15], rB[15];
    u64 facc = 0ull;

    // init: rows y0..y0+14 (always valid: y0+14 <= 462), immediate offsets
    #pragma unroll
    for (int j = 0; j < 15; ++j) {
        LOAD_ROW_AT(j * W);
        HORIZ_PAR(rA[j], rB[j]);
    }
    pp += 15 * W;

    // fast phases i = 1..45: in-bounds for EVERY tile (loads rows <= y0+59 <=
    // 507; outputs <= y0+44 <= 492). Iter (g,q): load row y0+15+15g+q (imm
    // offset q*W); VERT output y0+15g+q; insert into slot q.
    #pragma unroll
    for (int g = 0; g < 3; ++g) {
        #pragma unroll
        for (int q = 0; q < 15; ++q) {
            LOAD_ROW_AT(q * W);
            VERT(q);                       // output row y0 + 15g + q
            HORIZ_PAR(rA[q], rB[q]);       // insert row y0 + 15 + 15g + q
        }
        pp += 15 * W;
    }

    // epilogue: 11 rows, guards bind only for tile 8 (y0=448):
    // loads rows y0+60+q vs 512; outputs y0+45+q vs 498.
    #pragma unroll
    for (int q = 0; q < 11; ++q) {
        const bool dl = (y0 + 60 + q < W);
        const bool dv = (y0 + 45 + q < OUTW);
        if (dl) LOAD_ROW_AT(q * W);
        if (dv) VERT(q);                   // output row y0 + 45 + q
        if (dl) HORIZ_PAR(rA[q], rB[q]);   // insert row y0 + 60 + q
    }

    // deterministic block reduction in double
    {
        float flo, fhi;
        unpack2(facc, flo, fhi);
        red[t] = (double)flo + (double)fhi;
    }
    __syncthreads();
    #pragma unroll
    for (int s = 64; s > 0; s >>= 1) {
        if (t < s) red[t] += red[t + s];
        __syncthreads();
    }
    if (t == 0) {
        g_partials[batch * TILES_Y + tileY] = red[0];
        __threadfence();
        const int old = atomicAdd(&g_count[batch], 1);
        if (old == TILES_Y - 1) {   // last block for this batch: fixed-order sum
            __threadfence();
            double s = 0.0;
            #pragma unroll
            for (int i = 0; i < TILES_Y; ++i)
                s += __ldcg(&g_partials[batch * TILES_Y + i]);
            out[batch] = (float)(s * (1.0 / ((double)OUTW * (double)OUTW)));
            g_count[batch] = 0;     // reset for next graph replay
        }
    }
}

// ---------------------------------------------------------------------------
// Host side: replicate numpy float64 semantics exactly (validated R1-R16).
// ---------------------------------------------------------------------------

// numpy's pairwise_sum for contiguous float64 (PW_BLOCKSIZE = 128)
static double np_pairwise(const double* a, int n)
{
    if (n < 8) {
        double res = 0.0;
        for (int i = 0; i < n; ++i) res += a[i];
        return res;
    }
    else if (n <= 128) {
        double r[8];
        for (int j = 0; j < 8; ++j) r[j] = a[j];
        int i;
        for (i = 8; i < n - (n % 8); i += 8)
            for (int j = 0; j < 8; ++j) r[j] += a[i + j];
        double res = ((r[0] + r[1]) + (r[2] + r[3])) + ((r[4] + r[5]) + (r[6] + r[7]));
        for (; i < n; ++i) res += a[i];
        return res;
    }
    else {
        int n2 = n / 2;
        n2 -= n2 % 8;
        return np_pairwise(a, n2) + np_pairwise(a + n2, n - n2);
    }
}

extern "C" void kernel_launch(void* const* d_in, const int* in_sizes, int n_in,
                              void* d_out, int out_size)
{
    (void)in_sizes; (void)n_in; (void)out_size;
    const float* x  = (const float*)d_in[0];
    float*      out = (float*)d_out;

    const double sig     = 7.0 / 2.5;              // N=15//2=7; sig = N/2.5
    const double sig2    = pow(sig, 2.0);          // sig ** 2 (CPython float_pow -> libm pow)
    const double twosig2 = 2.0 * sig2;
    const double denomG  = (2.0 * M_PI) * sig;

    double Gy[225];
    for (int i = 0; i < 15; ++i) {
        const int yy = i - 7;
        for (int j = 0; j < 15; ++j) {
            const int xx = j - 7;
            const double G = exp((double)(-(xx * xx + yy * yy)) / twosig2) / denomG;
            Gy[i * 15 + j] = ((double)(-yy) * G) / sig2;
        }
    }
    const double s = np_pairwise(Gy, 225);         // np.sum(Gy), numpy pairwise order

    Weights wt;
    for (int j = 0; j < 8; ++j) {
        const int xx = j - 7;
        wt.hw[j] = (float)(exp((double)(-(xx * xx)) / twosig2) / denomG);
    }
    for (int k = 0; k < 7; ++k) {
        const int yy = k - 7;
        const double A = (((double)(-yy) * exp((double)(-(yy * yy)) / twosig2)) / sig2) / s;
        wt.vw[k] = (float)A;
    }

    dim3 grid(TILES_Y, NB);
    gder_kernel<<<grid, 128>>>(x, wt, out);
}